// round 10
// baseline (speedup 1.0000x reference)
#include <cuda_runtime.h>
#include <cuda_bf16.h>
#include <cstdint>

// WMAE: sum_{i,j} w[j%3] * |t1[i,j] - t2[i,j]| / n_sample, w = {300, 1, 200}
//
// At the LTS roofline: 100.66MB / 14.69us = 6.85 TB/s ≈ 6300 B/cyc @ ~1.09GHz
// (path-independent chip memory ceiling; both tensors must be read, L1 is
// flushed per launch -> byte count through LTS is invariant).
//
// This round: 512 blocks x 512 threads (same 262144 threads, same stride,
// same per-thread schedule of exactly 12 float4-pair loads) to halve the
// single-address tail-atomic train and the block-finish spread.
//
// Tail: ONE packed 64-bit atomic per block.
//   contribution = (1<<52) | round(block_sum * 2^10)
//   integer adds associative -> bitwise deterministic any arrival order;
//   final arrival's return value contains the complete total (no fence,
//   no re-read, no second reduction).

#define NBLOCKS 512
#define NTHREADS 512
#define FP_SCALE 1024.0       // 2^10
#define CNT_SHIFT 52
#define SUM_MASK ((1ULL << CNT_SHIFT) - 1ULL)

__device__ unsigned long long g_acc;   // packed {count[63:52], sum[51:0]}; zero-init; reset each replay

// pattern[v % 3] = weights for float4 #v (element indices 4v..4v+3); 4 ≡ 1 (mod 3)
__constant__ float4 c_pat[3] = {
    {300.0f, 1.0f, 200.0f, 300.0f},
    {1.0f, 200.0f, 300.0f, 1.0f},
    {200.0f, 300.0f, 1.0f, 200.0f}
};
__constant__ float c_w[3] = {300.0f, 1.0f, 200.0f};

__global__ __launch_bounds__(NTHREADS) void wmae_fused_kernel(
    const float* __restrict__ t1,
    const float* __restrict__ t2,
    float* __restrict__ out,
    int n)  // total element count
{
    const int n4 = n >> 2;
    const float4* __restrict__ a4 = reinterpret_cast<const float4*>(t1);
    const float4* __restrict__ b4 = reinterpret_cast<const float4*>(t2);

    const int stride = gridDim.x * blockDim.x;      // 262144, ≡ 1 (mod 3)
    const int tid0 = blockIdx.x * blockDim.x + threadIdx.x;

    float acc = 0.0f;
    int p = tid0 % 3;  // pattern index; advances by stride%3 == 1 per iteration
    for (int v = tid0; v < n4; v += stride) {
        float4 a = a4[v];          // default caching; LTS-cap bound
        float4 b = b4[v];
        float4 w = c_pat[p];
        acc = fmaf(w.x, fabsf(a.x - b.x), acc);
        acc = fmaf(w.y, fabsf(a.y - b.y), acc);
        acc = fmaf(w.z, fabsf(a.z - b.z), acc);
        acc = fmaf(w.w, fabsf(a.w - b.w), acc);
        p = (p == 2) ? 0 : p + 1;
    }

    // scalar tail (n % 4 != 0; n = 12,582,912 is divisible by 4 -> no-op here)
    if (blockIdx.x == 0 && threadIdx.x == 0) {
        for (int i = n4 << 2; i < n; i++) {
            acc = fmaf(c_w[i % 3], fabsf(t1[i] - t2[i]), acc);
        }
    }

    // block reduction (fp32, fixed order -> deterministic)
    __shared__ float sdata[NTHREADS / 32];
    #pragma unroll
    for (int off = 16; off > 0; off >>= 1)
        acc += __shfl_xor_sync(0xFFFFFFFFu, acc, off);
    const int lane = threadIdx.x & 31;
    const int wid = threadIdx.x >> 5;
    if (lane == 0) sdata[wid] = acc;
    __syncthreads();

    if (threadIdx.x == 0) {
        float bsum = sdata[0];
        #pragma unroll
        for (int w = 1; w < NTHREADS / 32; w++) bsum += sdata[w];

        // packed contribution: count=1 at bit 52, fixed-point sum below
        unsigned long long contrib =
            (1ULL << CNT_SHIFT) |
            (unsigned long long)__double2ll_rn((double)bsum * FP_SCALE);
        unsigned long long prev = atomicAdd(&g_acc, contrib);

        if ((prev >> CNT_SHIFT) == (unsigned long long)(gridDim.x - 1)) {
            // final arrival: total = prev + own contribution
            unsigned long long total_fixed = (prev + contrib) & SUM_MASK;
            long long n_sample = (long long)(n / 3);
            out[0] = (float)((double)total_fixed / FP_SCALE / (double)n_sample);
            g_acc = 0ULL;   // reset for next graph replay
        }
    }
}

extern "C" void kernel_launch(void* const* d_in, const int* in_sizes, int n_in,
                              void* d_out, int out_size) {
    const float* t1 = (const float*)d_in[0];
    const float* t2 = (const float*)d_in[1];
    float* out = (float*)d_out;
    int n = in_sizes[0];  // total elements (n_sample * 3)

    wmae_fused_kernel<<<NBLOCKS, NTHREADS>>>(t1, t2, out, n);
}